// round 4
// baseline (speedup 1.0000x reference)
#include <cuda_runtime.h>
#include <cstdint>

#define IN_C   256
#define OUT_C  128
#define NHEAD  4
#define MAX_N  131072
#define MAX_C  1024
#define TILE   32
#define CHUNK  256
#define HIST_ITEMS 4096

typedef unsigned long long u64;

// Scratch (static __device__ globals: allocation-free per harness rules)
__device__ float g_v[NHEAD * IN_C];
__device__ float g_c[NHEAD];
__device__ int   g_count[MAX_C];
__device__ int   g_offset[MAX_C + 1];
__device__ int   g_cursor[MAX_C];
__device__ int   g_sorted[MAX_N];

// ---------------------------------------------------------------------------
// packed f32x2 helpers (Blackwell FFMA2)
// ---------------------------------------------------------------------------
__device__ __forceinline__ void fma2(u64& d, u64 a, u64 b) {
    asm("fma.rn.f32x2 %0, %1, %2, %0;" : "+l"(d) : "l"(a), "l"(b));
}
__device__ __forceinline__ float2 unpk2(u64 v) {
    float lo, hi;
    asm("mov.b64 {%0, %1}, %2;" : "=f"(lo), "=f"(hi) : "l"(v));
    return make_float2(lo, hi);
}
union F4U2 { float4 f; ulonglong2 u; };
__device__ __forceinline__ ulonglong2 as_u2(float4 v) { F4U2 c; c.f = v; return c.u; }

// ---------------------------------------------------------------------------
// cp.async helpers (16B, zero-fill when sz==0)
// ---------------------------------------------------------------------------
__device__ __forceinline__ void cp_async16(uint32_t dst_sa, const void* src, int sz) {
    asm volatile("cp.async.cg.shared.global [%0], [%1], 16, %2;"
                 :: "r"(dst_sa), "l"(src), "r"(sz));
}
__device__ __forceinline__ void cp_commit() {
    asm volatile("cp.async.commit_group;");
}
__device__ __forceinline__ void cp_wait0() {
    asm volatile("cp.async.wait_group 0;");
}

// ---------------------------------------------------------------------------
// K1: fused prep (blocks 0..3) + smem-privatized histogram (blocks 4..)
// ---------------------------------------------------------------------------
__global__ __launch_bounds__(256) void k_prep_hist(
        const float* __restrict__ W_lin,
        const float* __restrict__ b_lin,
        const float* __restrict__ W_att,
        const float* __restrict__ b_att,
        const int* __restrict__ y,
        int n, int num_classes) {
    const int t = threadIdx.x;

    if (blockIdx.x < NHEAD) {
        const int h = blockIdx.x;
        float s = 0.0f;
#pragma unroll 4
        for (int o = 0; o < OUT_C; ++o) {
            s += W_lin[(size_t)(h * OUT_C + o) * IN_C + t] * __ldg(&W_att[o]);
        }
        g_v[h * IN_C + t] = s;

        if (t < 32) {
            float cs = 0.0f;
            for (int o = t; o < OUT_C; o += 32)
                cs += b_lin[h * OUT_C + o] * W_att[o];
#pragma unroll
            for (int d = 16; d; d >>= 1)
                cs += __shfl_xor_sync(0xffffffffu, cs, d);
            if (t == 0) g_c[h] = cs + b_att[0];
        }
        return;
    }

    __shared__ int scnt[MAX_C];
    for (int c = t; c < num_classes; c += 256) scnt[c] = 0;
    __syncthreads();

    const int base = (blockIdx.x - NHEAD) * HIST_ITEMS;
#pragma unroll
    for (int k = 0; k < HIST_ITEMS / 256; ++k) {
        const int i = base + k * 256 + t;
        if (i < n) atomicAdd(&scnt[y[i]], 1);
    }
    __syncthreads();

    for (int c = t; c < num_classes; c += 256) {
        const int v = scnt[c];
        if (v) atomicAdd(&g_count[c], v);
    }
}

// ---------------------------------------------------------------------------
// K2: exclusive scan of counts (single block)
// ---------------------------------------------------------------------------
__global__ void k_scan(int num_classes) {
    __shared__ int sm[1024];
    const int t = threadIdx.x;
    int val = (t < num_classes) ? g_count[t] : 0;
    sm[t] = val;
    __syncthreads();
#pragma unroll
    for (int d = 1; d < 1024; d <<= 1) {
        int x = (t >= d) ? sm[t - d] : 0;
        __syncthreads();
        sm[t] += x;
        __syncthreads();
    }
    if (t < num_classes) {
        int off = sm[t] - val;
        g_offset[t] = off;
        g_cursor[t] = off;
    }
    if (t == num_classes - 1) g_offset[num_classes] = sm[t];
}

// ---------------------------------------------------------------------------
// K3: two-level scatter
// ---------------------------------------------------------------------------
__global__ __launch_bounds__(256) void k_scatter(const int* __restrict__ y,
                                                 int n, int num_classes) {
    __shared__ int scur[MAX_C];
    const int t = threadIdx.x;
    const int base = blockIdx.x * HIST_ITEMS;

    for (int c = t; c < num_classes; c += 256) scur[c] = 0;
    __syncthreads();

    int yv[HIST_ITEMS / 256];
#pragma unroll
    for (int k = 0; k < HIST_ITEMS / 256; ++k) {
        const int i = base + k * 256 + t;
        yv[k] = (i < n) ? y[i] : -1;
        if (yv[k] >= 0) atomicAdd(&scur[yv[k]], 1);
    }
    __syncthreads();

    for (int c = t; c < num_classes; c += 256) {
        const int v = scur[c];
        if (v) scur[c] = atomicAdd(&g_cursor[c], v);
    }
    __syncthreads();

#pragma unroll
    for (int k = 0; k < HIST_ITEMS / 256; ++k) {
        if (yv[k] >= 0) {
            const int pos = atomicAdd(&scur[yv[k]], 1);
            g_sorted[pos] = base + k * 256 + t;
        }
    }
}

// ---------------------------------------------------------------------------
// K4: fused score+softmax+pool. One block per class, cp.async double-buffer.
//
// smem (floats):
//   sv   [0,1024)       v weights [4][256]
//   part [1024,2048)    score partials [w=8][r=32] float4; reused as sdr at end
//   se   [2048,2304)    duplicated e: row r -> (e0,e0,e1,e1),(e2,e2,e3,e3)
//   sidx [2304,2560)    member-index window (as int)
//   rows [2560,+16384)  two tile buffers; row r chunk c at (c ^ (r&7))
// rows reused as red[rg=4][h=4][col=256] for the final reduction.
//
// Score mapping: lane = row (32 rows/warp-view); warp w owns chunks {w+8j}.
//   -> v loads are warp-broadcast (1 wavefront), x loads conflict-free.
// ---------------------------------------------------------------------------
__global__ void __launch_bounds__(256) k_pool(const float* __restrict__ H,
                                              float* __restrict__ out) {
    extern __shared__ float smf[];
    float* sv   = smf;
    float* part = smf + 1024;
    float* se   = smf + 2048;
    int*   sidx = (int*)(smf + 2304);
    float* rows = smf + 2560;

    float4*       rows4 = (float4*)rows;
    const float4* sv4   = (const float4*)sv;
    float4*       part4 = (float4*)part;
    float4*       se4   = (float4*)se;
    const uint32_t rows_sa = (uint32_t)__cvta_generic_to_shared(rows);

    const int tid  = threadIdx.x;
    const int cls  = blockIdx.x;
    const int warp = tid >> 5;
    const int lane = tid & 31;

    const int beg = g_offset[cls];
    const int cnt = g_offset[cls + 1] - beg;

    for (int i = tid; i < NHEAD * IN_C; i += 256) sv[i] = g_v[i];
    float cb[NHEAD];
#pragma unroll
    for (int h = 0; h < NHEAD; ++h) cb[h] = g_c[h];

    u64 acc2[NHEAD][2];
#pragma unroll
    for (int h = 0; h < NHEAD; ++h) { acc2[h][0] = 0ull; acc2[h][1] = 0ull; }
    float dsum[NHEAD] = {0.f, 0.f, 0.f, 0.f};

    for (int c0 = 0; c0 < cnt; c0 += CHUNK) {
        const int chunkN = min(CHUNK, cnt - c0);
        __syncthreads();
        if (tid < chunkN) sidx[tid] = g_sorted[beg + c0 + tid];
        __syncthreads();

        const int nt = (chunkN + TILE - 1) / TILE;

        // ---- stage tile 0 into buffer 0 ----
        {
#pragma unroll
            for (int rr = 0; rr < 4; ++rr) {
                const int r  = warp * 4 + rr;
                const bool valid = r < chunkN;
                const char* src = (const char*)(H +
                    (valid ? (size_t)sidx[r] * IN_C : (size_t)0));
                const int sz = valid ? 16 : 0;
                const int d0 = r * 64 + (lane ^ (r & 7));
                const int d1 = r * 64 + ((lane + 32) ^ (r & 7));
                cp_async16(rows_sa + d0 * 16, src + lane * 16, sz);
                cp_async16(rows_sa + d1 * 16, src + (lane + 32) * 16, sz);
            }
            cp_commit();
        }

        for (int ti = 0; ti < nt; ++ti) {
            const int b = ti & 1;
            const float4* rb = rows4 + b * 2048;

            cp_wait0();
            __syncthreads();   // S1: tile ti resident; prev accumulate done

            // ---- score partials: lane=row, warp owns chunks {warp+8j} ----
            {
                u64 sa[NHEAD], sb[NHEAD];
#pragma unroll
                for (int h = 0; h < NHEAD; ++h) { sa[h] = 0ull; sb[h] = 0ull; }
                const int sw = lane & 7;
                const float4* rrow = rb + lane * 64;
#pragma unroll
                for (int j = 0; j < 8; ++j) {
                    const int c = warp + j * 8;
                    const ulonglong2 xu = as_u2(rrow[c ^ sw]);
#pragma unroll
                    for (int h = 0; h < NHEAD; ++h) {
                        const ulonglong2 vu = as_u2(sv4[h * 64 + c]);  // broadcast
                        fma2(sa[h], xu.x, vu.x);
                        fma2(sb[h], xu.y, vu.y);
                    }
                }
                float s[NHEAD];
#pragma unroll
                for (int h = 0; h < NHEAD; ++h) {
                    const float2 a = unpk2(sa[h]);
                    const float2 bq = unpk2(sb[h]);
                    s[h] = (a.x + a.y) + (bq.x + bq.y);
                }
                part4[warp * 32 + lane] = make_float4(s[0], s[1], s[2], s[3]);
            }

            // ---- prefetch tile ti+1 (overlaps reduce + accumulate) ----
            if (ti + 1 < nt) {
                const int bn = (ti + 1) & 1;
                const int t0 = (ti + 1) * TILE;
#pragma unroll
                for (int rr = 0; rr < 4; ++rr) {
                    const int r  = warp * 4 + rr;
                    const int gi = t0 + r;
                    const bool valid = gi < chunkN;
                    const char* src = (const char*)(H +
                        (valid ? (size_t)sidx[gi] * IN_C : (size_t)0));
                    const int sz = valid ? 16 : 0;
                    const int d0 = bn * 2048 + r * 64 + (lane ^ (r & 7));
                    const int d1 = bn * 2048 + r * 64 + ((lane + 32) ^ (r & 7));
                    cp_async16(rows_sa + d0 * 16, src + lane * 16, sz);
                    cp_async16(rows_sa + d1 * 16, src + (lane + 32) * 16, sz);
                }
                cp_commit();
            }
            __syncthreads();   // S2: partials visible

            // ---- reduce -> e (warp 0 only), store duplicated pairs ----
            if (tid < 32) {
                float4 a = part4[tid];
#pragma unroll
                for (int w = 1; w < 8; ++w) {
                    const float4 p = part4[w * 32 + tid];
                    a.x += p.x; a.y += p.y; a.z += p.z; a.w += p.w;
                }
                const bool valid = (c0 + ti * TILE + tid) < cnt;
                float e[NHEAD];
                const float s[NHEAD] = {a.x, a.y, a.z, a.w};
#pragma unroll
                for (int h = 0; h < NHEAD; ++h) {
                    float sc = s[h] + cb[h];
                    sc = (sc >= 0.0f) ? sc : 0.2f * sc;   // leaky_relu(0.2)
                    e[h] = valid ? __expf(sc) : 0.0f;     // tiny scores: ratio-safe
                    dsum[h] += e[h];
                }
                se4[tid * 2 + 0] = make_float4(e[0], e[0], e[1], e[1]);
                se4[tid * 2 + 1] = make_float4(e[2], e[2], e[3], e[3]);
            }
            __syncthreads();   // S3: se visible

            // ---- accumulate: thread (cg=tid&63, rg=tid>>6), 8 rows ----
            {
                const int cg = tid & 63;
                const int rg = tid >> 6;
#pragma unroll
                for (int rr = 0; rr < 8; ++rr) {
                    const int r = rg * 8 + rr;
                    const ulonglong2 xu = as_u2(rb[r * 64 + (cg ^ (r & 7))]);
                    const ulonglong2 e01 = as_u2(se4[r * 2 + 0]);  // (e0,e0,e1,e1)
                    const ulonglong2 e23 = as_u2(se4[r * 2 + 1]);  // (e2,e2,e3,e3)
                    fma2(acc2[0][0], e01.x, xu.x); fma2(acc2[0][1], e01.x, xu.y);
                    fma2(acc2[1][0], e01.y, xu.x); fma2(acc2[1][1], e01.y, xu.y);
                    fma2(acc2[2][0], e23.x, xu.x); fma2(acc2[2][1], e23.x, xu.y);
                    fma2(acc2[3][0], e23.y, xu.x); fma2(acc2[3][1], e23.y, xu.y);
                }
            }
            // next iteration's S1 protects buffer reuse
        }
    }

    __syncthreads();   // all tiles done everywhere; part/rows free for reuse

    // ---- final reduction ----
    if (tid < 32) {    // warp 0 holds dsum; sdr overlaid on part
        part4[tid] = make_float4(dsum[0], dsum[1], dsum[2], dsum[3]);
    }
    const int cg = tid & 63;
    const int rg = tid >> 6;
    float* red = rows;
#pragma unroll
    for (int h = 0; h < NHEAD; ++h) {
        const float2 p0 = unpk2(acc2[h][0]);
        const float2 p1 = unpk2(acc2[h][1]);
        float* dst = &red[(rg * NHEAD + h) * IN_C + cg * 4];
        dst[0] = p0.x; dst[1] = p0.y; dst[2] = p1.x; dst[3] = p1.y;
    }
    __syncthreads();

    if (tid < NHEAD) {
        float d = 0.0f;
        for (int r = 0; r < 32; ++r) d += part[r * 4 + tid];
        se[tid] = d;
    }
    __syncthreads();

    const int col = tid;
#pragma unroll
    for (int h = 0; h < NHEAD; ++h) {
        const float den = se[h];
        float s = red[(0 * NHEAD + h) * IN_C + col]
                + red[(1 * NHEAD + h) * IN_C + col]
                + red[(2 * NHEAD + h) * IN_C + col]
                + red[(3 * NHEAD + h) * IN_C + col];
        out[(size_t)cls * (NHEAD * IN_C) + h * IN_C + col] =
            (den > 0.0f) ? (s / den) : 0.0f;
    }
}

// ---------------------------------------------------------------------------
extern "C" void kernel_launch(void* const* d_in, const int* in_sizes, int n_in,
                              void* d_out, int out_size) {
    const float* H     = (const float*)d_in[0];
    const float* W_lin = (const float*)d_in[1];
    const float* b_lin = (const float*)d_in[2];
    const float* W_att = (const float*)d_in[3];
    const float* b_att = (const float*)d_in[4];
    const int*   y     = (const int*)d_in[5];
    float*       out   = (float*)d_out;

    const int N = in_sizes[0] / IN_C;
    const int num_classes = out_size / (NHEAD * IN_C);
    const int hist_blocks = (N + HIST_ITEMS - 1) / HIST_ITEMS;

    void* cnt_ptr = nullptr;
    cudaGetSymbolAddress(&cnt_ptr, g_count);
    cudaMemsetAsync(cnt_ptr, 0, num_classes * sizeof(int));

    const int smem_bytes = (2560 + 2 * TILE * IN_C) * (int)sizeof(float); // 75776
    cudaFuncSetAttribute(k_pool, cudaFuncAttributeMaxDynamicSharedMemorySize,
                         smem_bytes);

    k_prep_hist<<<NHEAD + hist_blocks, 256>>>(W_lin, b_lin, W_att, b_att,
                                              y, N, num_classes);
    k_scan<<<1, 1024>>>(num_classes);
    k_scatter<<<hist_blocks, 256>>>(y, N, num_classes);
    k_pool<<<num_classes, 256, smem_bytes>>>(H, out);
    (void)n_in;
}

// round 5
// speedup vs baseline: 1.0523x; 1.0523x over previous
#include <cuda_runtime.h>
#include <cstdint>

#define IN_C   256
#define OUT_C  128
#define NHEAD  4
#define MAX_N  131072
#define MAX_C  1024
#define TILE   32
#define CHUNK  256
#define HIST_ITEMS 1024

// Scratch (static __device__ globals: allocation-free per harness rules)
__device__ float g_v[NHEAD * IN_C];
__device__ float g_c[NHEAD];
__device__ int   g_count[MAX_C];
__device__ int   g_offset[MAX_C + 1];
__device__ int   g_cursor[MAX_C];
__device__ int   g_sorted[MAX_N];

// ---------------------------------------------------------------------------
// cp.async helpers (16B, zero-fill when sz==0)
// ---------------------------------------------------------------------------
__device__ __forceinline__ void cp_async16(uint32_t dst_sa, const void* src, int sz) {
    asm volatile("cp.async.cg.shared.global [%0], [%1], 16, %2;"
                 :: "r"(dst_sa), "l"(src), "r"(sz));
}
__device__ __forceinline__ void cp_commit() {
    asm volatile("cp.async.commit_group;");
}
__device__ __forceinline__ void cp_wait0() {
    asm volatile("cp.async.wait_group 0;");
}

// ---------------------------------------------------------------------------
// K1: fused prep (blocks 0..3) + smem-privatized histogram (blocks 4..)
// ---------------------------------------------------------------------------
__global__ __launch_bounds__(256) void k_prep_hist(
        const float* __restrict__ W_lin,
        const float* __restrict__ b_lin,
        const float* __restrict__ W_att,
        const float* __restrict__ b_att,
        const int* __restrict__ y,
        int n, int num_classes) {
    const int t = threadIdx.x;

    if (blockIdx.x < NHEAD) {
        const int h = blockIdx.x;
        float s = 0.0f;
#pragma unroll 4
        for (int o = 0; o < OUT_C; ++o) {
            s += W_lin[(size_t)(h * OUT_C + o) * IN_C + t] * __ldg(&W_att[o]);
        }
        g_v[h * IN_C + t] = s;

        if (t < 32) {
            float cs = 0.0f;
            for (int o = t; o < OUT_C; o += 32)
                cs += b_lin[h * OUT_C + o] * W_att[o];
#pragma unroll
            for (int d = 16; d; d >>= 1)
                cs += __shfl_xor_sync(0xffffffffu, cs, d);
            if (t == 0) g_c[h] = cs + b_att[0];
        }
        return;
    }

    __shared__ int scnt[MAX_C];
    for (int c = t; c < num_classes; c += 256) scnt[c] = 0;
    __syncthreads();

    const int base = (blockIdx.x - NHEAD) * HIST_ITEMS;
#pragma unroll
    for (int k = 0; k < HIST_ITEMS / 256; ++k) {
        const int i = base + k * 256 + t;
        if (i < n) atomicAdd(&scnt[y[i]], 1);
    }
    __syncthreads();

    for (int c = t; c < num_classes; c += 256) {
        const int v = scnt[c];
        if (v) atomicAdd(&g_count[c], v);
    }
}

// ---------------------------------------------------------------------------
// K2: exclusive scan of counts (single block)
// ---------------------------------------------------------------------------
__global__ void k_scan(int num_classes) {
    __shared__ int sm[1024];
    const int t = threadIdx.x;
    int val = (t < num_classes) ? g_count[t] : 0;
    sm[t] = val;
    __syncthreads();
#pragma unroll
    for (int d = 1; d < 1024; d <<= 1) {
        int x = (t >= d) ? sm[t - d] : 0;
        __syncthreads();
        sm[t] += x;
        __syncthreads();
    }
    if (t < num_classes) {
        int off = sm[t] - val;
        g_offset[t] = off;
        g_cursor[t] = off;
    }
    if (t == num_classes - 1) g_offset[num_classes] = sm[t];
}

// ---------------------------------------------------------------------------
// K3: two-level scatter (block: smem hist -> one global reservation per
// present class -> smem-cursor local scatter)
// ---------------------------------------------------------------------------
__global__ __launch_bounds__(256) void k_scatter(const int* __restrict__ y,
                                                 int n, int num_classes) {
    __shared__ int scur[MAX_C];
    const int t = threadIdx.x;
    const int base = blockIdx.x * HIST_ITEMS;

    for (int c = t; c < num_classes; c += 256) scur[c] = 0;
    __syncthreads();

    int yv[HIST_ITEMS / 256];
#pragma unroll
    for (int k = 0; k < HIST_ITEMS / 256; ++k) {
        const int i = base + k * 256 + t;
        yv[k] = (i < n) ? y[i] : -1;
        if (yv[k] >= 0) atomicAdd(&scur[yv[k]], 1);
    }
    __syncthreads();

    for (int c = t; c < num_classes; c += 256) {
        const int v = scur[c];
        if (v) scur[c] = atomicAdd(&g_cursor[c], v);
    }
    __syncthreads();

#pragma unroll
    for (int k = 0; k < HIST_ITEMS / 256; ++k) {
        if (yv[k] >= 0) {
            const int pos = atomicAdd(&scur[yv[k]], 1);
            g_sorted[pos] = base + k * 256 + t;
        }
    }
}

// ---------------------------------------------------------------------------
// K4: fused score+softmax+pool. One block per class, cp.async double-buffer,
// 2 barriers per tile.
//
// smem (floats):
//   sv   [0,1024)        v weights [4][256]; sv[0..3] reused as denom at end
//   se   [1024,1152)     e per row: se4[r] = (e0,e1,e2,e3); reused for dsum
//   sidx [1152,1408)     member-index window (int)
//   rows [1536,+16384)   two tile buffers; row r chunk c at (c ^ (r&7))
// rows buffer 0 reused as red[rg=4][h=4][col=256] for the final reduction.
//
// Score mapping: thread (w,lane): row = w*4 + (lane>>3), chunk set
// {(lane&7) + 8j}. 8-lane shfl tree reduces the dot product; the group lead
// (lane&7==0) applies leaky+exp and writes se4[row].
// ---------------------------------------------------------------------------
__global__ void __launch_bounds__(256) k_pool(const float* __restrict__ H,
                                              float* __restrict__ out) {
    extern __shared__ float smf[];
    float* sv   = smf;
    float* se   = smf + 1024;
    int*   sidx = (int*)(smf + 1152);
    float* rows = smf + 1536;

    float4*       rows4 = (float4*)rows;
    const float4* sv4   = (const float4*)sv;
    float4*       se4   = (float4*)se;
    const uint32_t rows_sa = (uint32_t)__cvta_generic_to_shared(rows);

    const int tid   = threadIdx.x;
    const int cls   = blockIdx.x;
    const int warp  = tid >> 5;
    const int lane  = tid & 31;
    const int lane8 = lane & 7;             // chunk segment
    const int rloc  = warp * 4 + (lane >> 3);  // scored row

    const int beg = g_offset[cls];
    const int cnt = g_offset[cls + 1] - beg;

    for (int i = tid; i < NHEAD * IN_C; i += 256) sv[i] = g_v[i];
    float cb[NHEAD];
#pragma unroll
    for (int h = 0; h < NHEAD; ++h) cb[h] = g_c[h];

    float acc[NHEAD][4];
#pragma unroll
    for (int h = 0; h < NHEAD; ++h)
#pragma unroll
        for (int j = 0; j < 4; ++j) acc[h][j] = 0.0f;
    float dsum[NHEAD] = {0.f, 0.f, 0.f, 0.f};

    for (int c0 = 0; c0 < cnt; c0 += CHUNK) {
        const int chunkN = min(CHUNK, cnt - c0);
        __syncthreads();
        if (tid < chunkN) sidx[tid] = g_sorted[beg + c0 + tid];
        __syncthreads();

        const int nt = (chunkN + TILE - 1) / TILE;

        // ---- stage tile 0 into buffer 0 ----
#pragma unroll
        for (int rr = 0; rr < 4; ++rr) {
            const int r = warp * 4 + rr;
            const bool valid = r < chunkN;
            const char* src = (const char*)(H +
                (valid ? (size_t)sidx[r] * IN_C : (size_t)0));
            const int sz = valid ? 16 : 0;
            const int d0 = r * 64 + (lane ^ (r & 7));
            const int d1 = r * 64 + ((lane + 32) ^ (r & 7));
            cp_async16(rows_sa + d0 * 16, src + lane * 16, sz);
            cp_async16(rows_sa + d1 * 16, src + (lane + 32) * 16, sz);
        }
        cp_commit();

        for (int ti = 0; ti < nt; ++ti) {
            const int b = ti & 1;
            const float4* rb = rows4 + b * 2048;

            cp_wait0();
            __syncthreads();   // S1: tile ti resident; prev accumulate done

            // ---- prefetch tile ti+1 (overlaps score+reduce+accumulate) ----
            if (ti + 1 < nt) {
                const int bn = (ti + 1) & 1;
                const int t0 = (ti + 1) * TILE;
#pragma unroll
                for (int rr = 0; rr < 4; ++rr) {
                    const int r  = warp * 4 + rr;
                    const int gi = t0 + r;
                    const bool valid = gi < chunkN;
                    const char* src = (const char*)(H +
                        (valid ? (size_t)sidx[gi] * IN_C : (size_t)0));
                    const int sz = valid ? 16 : 0;
                    const int d0 = bn * 2048 + r * 64 + (lane ^ (r & 7));
                    const int d1 = bn * 2048 + r * 64 + ((lane + 32) ^ (r & 7));
                    cp_async16(rows_sa + d0 * 16, src + lane * 16, sz);
                    cp_async16(rows_sa + d1 * 16, src + (lane + 32) * 16, sz);
                }
                cp_commit();
            }

            // ---- score: 8-lane group per row ----
            {
                float s[NHEAD] = {0.f, 0.f, 0.f, 0.f};
                const int sw = rloc & 7;
                const float4* rrow = rb + rloc * 64;
#pragma unroll
                for (int j = 0; j < 8; ++j) {
                    const int c = lane8 + 8 * j;
                    const float4 x = rrow[c ^ sw];
#pragma unroll
                    for (int h = 0; h < NHEAD; ++h) {
                        const float4 v = sv4[h * 64 + c];
                        s[h] += x.x * v.x + x.y * v.y + x.z * v.z + x.w * v.w;
                    }
                }
#pragma unroll
                for (int h = 0; h < NHEAD; ++h) {
                    s[h] += __shfl_xor_sync(0xffffffffu, s[h], 4);
                    s[h] += __shfl_xor_sync(0xffffffffu, s[h], 2);
                    s[h] += __shfl_xor_sync(0xffffffffu, s[h], 1);
                }
                if (lane8 == 0) {
                    const bool valid = (c0 + ti * TILE + rloc) < cnt;
                    float e[NHEAD];
#pragma unroll
                    for (int h = 0; h < NHEAD; ++h) {
                        float sc = s[h] + cb[h];
                        sc = (sc >= 0.0f) ? sc : 0.2f * sc;  // leaky_relu(0.2)
                        e[h] = valid ? __expf(sc) : 0.0f;    // tiny scores: ratio-safe
                        dsum[h] += e[h];
                    }
                    se4[rloc] = make_float4(e[0], e[1], e[2], e[3]);
                }
            }
            __syncthreads();   // S2: se visible

            // ---- accumulate: thread (cg=tid&63, rg=tid>>6), 8 rows ----
            {
                const int cg = tid & 63;
                const int rg = tid >> 6;
#pragma unroll
                for (int rr = 0; rr < 8; ++rr) {
                    const int    r = rg * 8 + rr;
                    const float4 x = rb[r * 64 + (cg ^ (r & 7))];
                    const float4 e = se4[r];
                    acc[0][0] += e.x * x.x; acc[0][1] += e.x * x.y;
                    acc[0][2] += e.x * x.z; acc[0][3] += e.x * x.w;
                    acc[1][0] += e.y * x.x; acc[1][1] += e.y * x.y;
                    acc[1][2] += e.y * x.z; acc[1][3] += e.y * x.w;
                    acc[2][0] += e.z * x.x; acc[2][1] += e.z * x.y;
                    acc[2][2] += e.z * x.z; acc[2][3] += e.z * x.w;
                    acc[3][0] += e.w * x.x; acc[3][1] += e.w * x.y;
                    acc[3][2] += e.w * x.z; acc[3][3] += e.w * x.w;
                }
            }
            // next iter's S1 protects buffer/se reuse
        }
    }

    __syncthreads();   // all accumulates done; se/sv/rows free for reuse

    // ---- denom: 32 group-leads hold dsum partials ----
    if (lane8 == 0) se4[rloc] = make_float4(dsum[0], dsum[1], dsum[2], dsum[3]);
    const int cg = tid & 63;
    const int rg = tid >> 6;
    float* red = rows;   // buffer 0 as red[rg][h][col]
#pragma unroll
    for (int h = 0; h < NHEAD; ++h) {
        float* dst = &red[(rg * NHEAD + h) * IN_C + cg * 4];
        dst[0] = acc[h][0]; dst[1] = acc[h][1];
        dst[2] = acc[h][2]; dst[3] = acc[h][3];
    }
    __syncthreads();

    if (tid < NHEAD) {
        float d = 0.0f;
        for (int r = 0; r < 32; ++r) d += se[r * 4 + tid];
        sv[tid] = d;
    }
    __syncthreads();

    const int col = tid;
#pragma unroll
    for (int h = 0; h < NHEAD; ++h) {
        const float den = sv[h];
        float s = red[(0 * NHEAD + h) * IN_C + col]
                + red[(1 * NHEAD + h) * IN_C + col]
                + red[(2 * NHEAD + h) * IN_C + col]
                + red[(3 * NHEAD + h) * IN_C + col];
        out[(size_t)cls * (NHEAD * IN_C) + h * IN_C + col] =
            (den > 0.0f) ? (s / den) : 0.0f;
    }
}

// ---------------------------------------------------------------------------
extern "C" void kernel_launch(void* const* d_in, const int* in_sizes, int n_in,
                              void* d_out, int out_size) {
    const float* H     = (const float*)d_in[0];
    const float* W_lin = (const float*)d_in[1];
    const float* b_lin = (const float*)d_in[2];
    const float* W_att = (const float*)d_in[3];
    const float* b_att = (const float*)d_in[4];
    const int*   y     = (const int*)d_in[5];
    float*       out   = (float*)d_out;

    const int N = in_sizes[0] / IN_C;
    const int num_classes = out_size / (NHEAD * IN_C);
    const int hist_blocks = (N + HIST_ITEMS - 1) / HIST_ITEMS;

    void* cnt_ptr = nullptr;
    cudaGetSymbolAddress(&cnt_ptr, g_count);
    cudaMemsetAsync(cnt_ptr, 0, num_classes * sizeof(int));

    const int smem_bytes = (1536 + 2 * TILE * IN_C) * (int)sizeof(float); // 71680
    cudaFuncSetAttribute(k_pool, cudaFuncAttributeMaxDynamicSharedMemorySize,
                         smem_bytes);

    k_prep_hist<<<NHEAD + hist_blocks, 256>>>(W_lin, b_lin, W_att, b_att,
                                              y, N, num_classes);
    k_scan<<<1, 1024>>>(num_classes);
    k_scatter<<<hist_blocks, 256>>>(y, N, num_classes);
    k_pool<<<num_classes, 256, smem_bytes>>>(H, out);
    (void)n_in;
}